// round 14
// baseline (speedup 1.0000x reference)
#include <cuda_runtime.h>
#include <cuda_bf16.h>
#include <cuda_fp16.h>
#include <cstdint>

// ======================= problem sizes (fixed by dataset) ====================
#define TOKENS 4096
#define IC     4096
#define OC     4096

// Tiles: 1024 = 32x32 of 128x128. [0,888): direct (3.0 exact waves at
// 2 CTA/SM x 148 SM). [888,1024): 136 tail tiles, each split into 2 K-slices
// (K=2048 each) -> 272 CTAs fill wave 4 at half duration; fixup adds halves.
#define N_BIG   888
#define N_TAIL  (1024 - N_BIG)          // 136

// ======================= device scratch (no runtime alloc) ==================
__device__ uint16_t g_x16[(size_t)TOKENS * IC];  // 32 MB  x as fp16
__device__ uint16_t g_s16[(size_t)OC * IC];      // 32 MB  B = sign / (ow/s) fp16
__device__ float g_scale[OC];   // 0 -> 1 (exact: then all signs are 0)
__device__ float g_part[2][(size_t)N_TAIL * 128 * 128];  // 2 x 8.9 MB partials

// ======================= helpers =============================================
__device__ __forceinline__ uint32_t smem_u32(const void* p) {
    uint32_t a;
    asm("{ .reg .u64 t; cvta.to.shared.u64 t, %1; cvt.u32.u64 %0, t; }"
        : "=r"(a) : "l"(p));
    return a;
}

#define CP_ASYNC16(saddr, gaddr) \
    asm volatile("cp.async.cg.shared.global [%0], [%1], 16;" \
                 :: "r"(saddr), "l"(gaddr))
#define CP_COMMIT() asm volatile("cp.async.commit_group;" ::: "memory")
#define CP_WAIT1()  asm volatile("cp.async.wait_group 1;" ::: "memory")

#define LDMATRIX_X4(r0, r1, r2, r3, addr) \
    asm volatile("ldmatrix.sync.aligned.m8n8.x4.shared.b16 {%0,%1,%2,%3}, [%4];" \
                 : "=r"(r0), "=r"(r1), "=r"(r2), "=r"(r3) : "r"(addr))

#define MMA_F16(d, a, b0, b1) \
    asm volatile("mma.sync.aligned.m16n8k16.row.col.f32.f16.f16.f32 " \
                 "{%0,%1,%2,%3}, {%4,%5,%6,%7}, {%8,%9}, {%0,%1,%2,%3};" \
                 : "+f"((d)[0]), "+f"((d)[1]), "+f"((d)[2]), "+f"((d)[3]) \
                 : "r"((a)[0]), "r"((a)[1]), "r"((a)[2]), "r"((a)[3]), \
                   "r"(b0), "r"(b1))

// ======================= prep kernels ========================================
__global__ void __launch_bounds__(256) stats_ws_kernel(
    const float* __restrict__ w, const float* __restrict__ ow,
    const int* __restrict__ idx, int nout) {
    __shared__ float red[16];
    const int o = blockIdx.x, tid = threadIdx.x;
    const int lane = tid & 31, warp = tid >> 5;

    const float4* row = (const float4*)(w + (size_t)o * IC);
    float4 v[4];
    float s = 0.f;
#pragma unroll
    for (int i = 0; i < 4; ++i) {
        v[i] = row[tid + 256 * i];
        s += v[i].x + v[i].y + v[i].z + v[i].w;
    }
#pragma unroll
    for (int d = 16; d > 0; d >>= 1) s += __shfl_xor_sync(0xffffffffu, s, d);
    if (lane == 0) red[warp] = s;
    __syncthreads();
    if (warp == 0) {
        float t = (lane < 8) ? red[lane] : 0.f;
#pragma unroll
        for (int d = 4; d > 0; d >>= 1) t += __shfl_xor_sync(0xffffffffu, t, d);
        if (lane == 0) red[8] = t;
    }
    __syncthreads();
    float mean = red[8] * (1.f / IC);

    float a = 0.f;
#pragma unroll
    for (int i = 0; i < 4; ++i)
        a += fabsf(v[i].x - mean) + fabsf(v[i].y - mean) +
             fabsf(v[i].z - mean) + fabsf(v[i].w - mean);
#pragma unroll
    for (int d = 16; d > 0; d >>= 1) a += __shfl_xor_sync(0xffffffffu, a, d);
    if (lane == 0) red[warp] = a;
    __syncthreads();
    if (warp == 0) {
        float t = (lane < 8) ? red[lane] : 0.f;
#pragma unroll
        for (int d = 4; d > 0; d >>= 1) t += __shfl_xor_sync(0xffffffffu, t, d);
        if (lane == 0) red[9] = t;
    }
    __syncthreads();
    float sc = red[9] * (1.f / IC);
    float s_eff = (sc == 0.f) ? 1.f : sc;
    if (tid == 0) g_scale[o] = s_eff;

    // Phase 1: pure sign row, vectorized, branch-free
#pragma unroll
    for (int i = 0; i < 4; ++i) {
        int e0 = (tid + 256 * i) * 4;
        float ev[4] = {v[i].x, v[i].y, v[i].z, v[i].w};
        uint16_t hv[4];
#pragma unroll
        for (int e = 0; e < 4; ++e) {
            float wc = ev[e] - mean;
            float sv = (wc > 0.f) ? 1.f : ((wc < 0.f) ? -1.f : 0.f);
            hv[e] = __half_as_ushort(__float2half_rn(sv));
        }
        uint2 pk;
        pk.x = (uint32_t)hv[0] | ((uint32_t)hv[1] << 16);
        pk.y = (uint32_t)hv[2] | ((uint32_t)hv[3] << 16);
        *(uint2*)(g_s16 + (size_t)o * IC + e0) = pk;
    }

    // Phase 2: overwrite outlier columns
    __syncthreads();
    if (tid < nout) {
        float sv = ow[(size_t)o * nout + tid] / s_eff;
        g_s16[(size_t)o * IC + idx[tid]] =
            __half_as_ushort(__float2half_rn(sv));
    }
}

__global__ void build_x_kernel(const float* __restrict__ x) {
    size_t base = ((size_t)blockIdx.x * 256 + threadIdx.x) * 8;
    float4 v0 = *(const float4*)(x + base);
    float4 v1 = *(const float4*)(x + base + 4);
    float e[8] = {v0.x, v0.y, v0.z, v0.w, v1.x, v1.y, v1.z, v1.w};
    uint16_t hv[8];
#pragma unroll
    for (int k = 0; k < 8; ++k) hv[k] = __half_as_ushort(__float2half_rn(e[k]));
    uint4 pk;
    pk.x = (uint32_t)hv[0] | ((uint32_t)hv[1] << 16);
    pk.y = (uint32_t)hv[2] | ((uint32_t)hv[3] << 16);
    pk.z = (uint32_t)hv[4] | ((uint32_t)hv[5] << 16);
    pk.w = (uint32_t)hv[6] | ((uint32_t)hv[7] << 16);
    *(uint4*)(g_x16 + base) = pk;
}

// ======================= GEMM ================================================
// CTA 128x128, BK=64, 3 stages, 2 CTAs/SM, single-barrier loop.
// Blocks [0,888): full K=4096, direct epilogue.
// Blocks [888,1160): tail tiles split 2-way in K; raw partials to g_part.
static constexpr int STAGE_BYTES = (128 + 128) * 64 * 2;  // 32768
static constexpr int OFF_B = 128 * 64 * 2;                 // 16384
static constexpr int SMEM_BYTES = 3 * STAGE_BYTES;         // 98304

__global__ void __launch_bounds__(256, 2)
gemm_kernel(float* __restrict__ out, const float* __restrict__ bias) {
    extern __shared__ __align__(1024) char smem[];
    const uint32_t sbase = smem_u32(smem);
    const int tid = threadIdx.x;
    const int wid = tid >> 5, lane = tid & 31;
    const int wm = wid >> 2, wn = wid & 3;

    int id, kbase, nt, slice;
    if (blockIdx.x < N_BIG) {
        id = blockIdx.x; kbase = 0; nt = 64; slice = -1;
    } else {
        int sid = blockIdx.x - N_BIG;          // 0..271
        id = N_BIG + (sid >> 1);
        slice = sid & 1;
        kbase = slice * 32; nt = 32;
    }
    const int bm = id >> 5, bn = id & 31;

    float acc[4][4][4];
#pragma unroll
    for (int i = 0; i < 4; ++i)
#pragma unroll
        for (int j = 0; j < 4; ++j)
#pragma unroll
            for (int k = 0; k < 4; ++k) acc[i][j][k] = 0.f;

    const uint16_t* Abase = g_x16 + (size_t)bm * 128 * IC;
    const uint16_t* Bbase = g_s16 + (size_t)bn * 128 * IC;

    auto issue = [&](int kt, int s) {
        const uint16_t* a = Abase + kt * 64;
        const uint16_t* b = Bbase + kt * 64;
        uint32_t st = sbase + s * STAGE_BYTES;
#pragma unroll
        for (int i = 0; i < 4; ++i) {
            int c = tid + i * 256;
            int row = c >> 3, ch = c & 7;
            uint32_t so = (uint32_t)row * 128 + (uint32_t)((ch ^ (row & 7)) << 4);
            CP_ASYNC16(st + so, a + (size_t)row * IC + ch * 8);
            CP_ASYNC16(st + OFF_B + so, b + (size_t)row * IC + ch * 8);
        }
    };

    auto compute = [&](int s) {
        uint32_t stA = sbase + s * STAGE_BYTES;
        uint32_t stB = stA + OFF_B;
#pragma unroll
        for (int ks = 0; ks < 4; ++ks) {
            uint32_t bfr[2][4];
#pragma unroll
            for (int nj = 0; nj < 2; ++nj) {
                int row = wn * 32 + nj * 16 + (lane & 7) + (((lane >> 4) & 1) << 3);
                int ch = ks * 2 + ((lane >> 3) & 1);
                uint32_t ad = stB + (uint32_t)row * 128 +
                              (uint32_t)((ch ^ (row & 7)) << 4);
                LDMATRIX_X4(bfr[nj][0], bfr[nj][1], bfr[nj][2], bfr[nj][3], ad);
            }
            uint32_t afr[4][4];
#pragma unroll
            for (int mi = 0; mi < 4; ++mi) {
                int row = wm * 64 + mi * 16 + (lane & 15);
                int ch = ks * 2 + (lane >> 4);
                uint32_t ad = stA + (uint32_t)row * 128 +
                              (uint32_t)((ch ^ (row & 7)) << 4);
                LDMATRIX_X4(afr[mi][0], afr[mi][1], afr[mi][2], afr[mi][3], ad);
            }
#pragma unroll
            for (int mi = 0; mi < 4; ++mi)
#pragma unroll
                for (int nf = 0; nf < 4; ++nf)
                    MMA_F16(acc[mi][nf], afr[mi],
                            bfr[nf >> 1][(nf & 1) * 2],
                            bfr[nf >> 1][(nf & 1) * 2 + 1]);
        }
    };

    issue(kbase + 0, 0); CP_COMMIT();
    issue(kbase + 1, 1); CP_COMMIT();
    for (int kt = 0; kt < nt; ++kt) {
        CP_WAIT1();
        __syncthreads();
        if (kt + 2 < nt) {
            issue(kbase + kt + 2, (kt + 2) % 3);
            CP_COMMIT();
        }
        compute(kt % 3);
    }

    if (slice < 0) {
        // ---- direct epilogue: out = acc * s_o + bias --------------------
#pragma unroll
        for (int nf = 0; nf < 4; ++nf) {
            int col = bn * 128 + wn * 32 + (nf >> 1) * 16 + (nf & 1) * 8 + 2 * (lane & 3);
            float s0 = g_scale[col], s1 = g_scale[col + 1];
            float b0 = __ldg(bias + col), b1 = __ldg(bias + col + 1);
#pragma unroll
            for (int mi = 0; mi < 4; ++mi) {
                int r0 = bm * 128 + wm * 64 + mi * 16 + (lane >> 2);
                float2 v0 = make_float2(acc[mi][nf][0] * s0 + b0,
                                        acc[mi][nf][1] * s1 + b1);
                *(float2*)(out + (size_t)r0 * OC + col) = v0;
                float2 v1 = make_float2(acc[mi][nf][2] * s0 + b0,
                                        acc[mi][nf][3] * s1 + b1);
                *(float2*)(out + (size_t)(r0 + 8) * OC + col) = v1;
            }
        }
    } else {
        // ---- split epilogue: raw partials, tile-local row-major ---------
        float* pb = g_part[slice] + (size_t)(id - N_BIG) * 128 * 128;
#pragma unroll
        for (int nf = 0; nf < 4; ++nf) {
            int lc = wn * 32 + (nf >> 1) * 16 + (nf & 1) * 8 + 2 * (lane & 3);
#pragma unroll
            for (int mi = 0; mi < 4; ++mi) {
                int lr = wm * 64 + mi * 16 + (lane >> 2);
                *(float2*)(pb + (size_t)lr * 128 + lc) =
                    make_float2(acc[mi][nf][0], acc[mi][nf][1]);
                *(float2*)(pb + (size_t)(lr + 8) * 128 + lc) =
                    make_float2(acc[mi][nf][2], acc[mi][nf][3]);
            }
        }
    }
}

// Fixup for tail tiles: out = (p0 + p1) * s_o + bias.
__global__ void __launch_bounds__(256) fixup_kernel(
    float* __restrict__ out, const float* __restrict__ bias) {
    size_t idx4 = ((size_t)blockIdx.x * 256 + threadIdx.x) * 4;
    int t = (int)(idx4 >> 14);            // tail tile index 0..135
    int lr = (int)((idx4 >> 7) & 127);    // local row
    int lc = (int)(idx4 & 127);           // local col (4 consecutive)
    int id = N_BIG + t;
    int bm = id >> 5, bn = id & 31;
    int row = bm * 128 + lr;
    int col = bn * 128 + lc;
    float4 p0 = *(const float4*)(g_part[0] + idx4);
    float4 p1 = *(const float4*)(g_part[1] + idx4);
    float4 o;
    o.x = (p0.x + p1.x) * g_scale[col + 0] + __ldg(bias + col + 0);
    o.y = (p0.y + p1.y) * g_scale[col + 1] + __ldg(bias + col + 1);
    o.z = (p0.z + p1.z) * g_scale[col + 2] + __ldg(bias + col + 2);
    o.w = (p0.w + p1.w) * g_scale[col + 3] + __ldg(bias + col + 3);
    *(float4*)(out + (size_t)row * OC + col) = o;
}

// ======================= launcher ============================================
extern "C" void kernel_launch(void* const* d_in, const int* in_sizes, int n_in,
                              void* d_out, int out_size) {
    const float* x = (const float*)d_in[0];
    const float* w = (const float*)d_in[1];
    const float* bias = (const float*)d_in[2];
    const float* ow = (const float*)d_in[3];
    const int* idx = (const int*)d_in[4];
    float* out = (float*)d_out;
    int nout = in_sizes[4];

    static bool attr_set = false;
    if (!attr_set) {
        cudaFuncSetAttribute(gemm_kernel,
                             cudaFuncAttributeMaxDynamicSharedMemorySize, SMEM_BYTES);
        attr_set = true;
    }

    stats_ws_kernel<<<OC, 256>>>(w, ow, idx, nout);
    build_x_kernel<<<(unsigned)((size_t)TOKENS * IC / 2048), 256>>>(x);

    gemm_kernel<<<N_BIG + 2 * N_TAIL, 256, SMEM_BYTES>>>(out, bias);
    // 136 tiles * 16384 elems / (256 threads * 4 elems) = 2176 blocks
    fixup_kernel<<<(N_TAIL * 128 * 128) / 1024, 256>>>(out, bias);
}